// round 13
// baseline (speedup 1.0000x reference)
#include <cuda_runtime.h>
#include <math.h>

// RecurrentAttention: B=128, S=8192, D=64
//   scores[b,s] = sum_d x[b,s,d] * v[d]
//   alpha[b,s]  = softmax_s(scores)
//   out[b,d]    = sum_s alpha[b,s] * x[b,s,d]
// Output layout: d_out[0..B*D) = out, d_out[B*D..B*D+B*S) = alpha.
//
// Two-kernel split-S design:
//  K1: grid = B*C CTAs (C=4 chunks of S), 512 threads. Single pass over x.
//      Half-warp-per-row scheme: one float4 LDG covers 2 rows (lanes 0-15 row
//      2j, lanes 16-31 row 2j+1, 4 dims/lane). Dot reduce = 4 shuffles for 2
//      rows. Branchless online softmax. Raw scores written (coalesced) into
//      the alpha buffer; per-CTA partial (m, l, acc[64]) to __device__ scratch.
//  K2: merge the C partials per batch, write out[b,:], transform raw scores
//      in-place into alpha = exp(s - M) / L.

#define BB 128
#define SS 8192
#define DD 64
#define CC 4                        // chunks per batch
#define ROWS_CTA (SS / CC)          // 2048
#define T1 512
#define W1 (T1 / 32)                // 16 warps
#define RPW (ROWS_CTA / W1)         // 128 rows per warp
#define PART_STRIDE 68              // m, l, acc[64], pad

__device__ float g_part[BB * CC * PART_STRIDE];

__global__ __launch_bounds__(T1, 3)
void ra_pass1(const float* __restrict__ x,
              const float* __restrict__ v,
              float* __restrict__ alpha)   // raw scores written here
{
    __shared__ float s_m[W1];
    __shared__ float s_l[W1];
    __shared__ float s_f[W1];
    __shared__ float s_acc[W1 * DD];

    const int bx    = blockIdx.x;
    const int b     = bx >> 2;
    const int chunk = bx & 3;
    const int tid   = threadIdx.x;
    const int w     = tid >> 5;
    const int lane  = tid & 31;
    const int li    = lane & 15;    // lane within half-warp
    const int h     = lane >> 4;    // which half (row parity)

    // 4 dims per lane
    const float4 vv = reinterpret_cast<const float4*>(v)[li];

    // this warp's 128 rows
    const float4* xp =
        reinterpret_cast<const float4*>(
            x + ((size_t)b * SS + (size_t)chunk * ROWS_CTA + (size_t)w * RPW) * DD)
        + (size_t)h * (DD / 4) + li;
    // row r (even base) lives at offset r*(DD/4)=r*16 float4

    float* score_out = alpha + (size_t)b * SS + (size_t)chunk * ROWS_CTA + (size_t)w * RPW;

    float m = -3.0e38f, l = 0.0f;
    float a0 = 0.f, a1 = 0.f, a2 = 0.f, a3 = 0.f;

    #pragma unroll
    for (int blk = 0; blk < RPW; blk += 32) {       // 32-row blocks
        float sreg = 0.0f;
        #pragma unroll
        for (int jj = 0; jj < 16; jj += 4) {        // row-pairs, 4 at a time
            float4 xv[4];
            #pragma unroll
            for (int u = 0; u < 4; u++)
                xv[u] = xp[(blk + 2 * (jj + u)) * (DD / 4)];

            #pragma unroll
            for (int u = 0; u < 4; u++) {
                float p = fmaf(xv[u].x, vv.x,
                          fmaf(xv[u].y, vv.y,
                          fmaf(xv[u].z, vv.z, xv[u].w * vv.w)));
                p += __shfl_xor_sync(0xffffffffu, p, 1);
                p += __shfl_xor_sync(0xffffffffu, p, 2);
                p += __shfl_xor_sync(0xffffffffu, p, 4);
                p += __shfl_xor_sync(0xffffffffu, p, 8);
                // all 16 lanes of each half now hold their row's score

                if (li == jj + u) sreg = p;         // rotate into writer lane

                // branchless online update (identical instrs, per-half data)
                float Mn   = fmaxf(m, p);
                float corr = __expf(m - Mn);
                float wt   = __expf(p - Mn);
                l  = fmaf(l,  corr, wt);
                a0 = fmaf(a0, corr, wt * xv[u].x);
                a1 = fmaf(a1, corr, wt * xv[u].y);
                a2 = fmaf(a2, corr, wt * xv[u].z);
                a3 = fmaf(a3, corr, wt * xv[u].w);
                m  = Mn;
            }
        }
        // coalesced 32-lane score write: lane L -> row blk + 2*(L&15) + (L>>4)
        score_out[blk + 2 * li + h] = sreg;
    }

    // merge the two half-warps (same dims, different rows)
    {
        float mo = __shfl_xor_sync(0xffffffffu, m,  16);
        float lo = __shfl_xor_sync(0xffffffffu, l,  16);
        float b0 = __shfl_xor_sync(0xffffffffu, a0, 16);
        float b1 = __shfl_xor_sync(0xffffffffu, a1, 16);
        float b2 = __shfl_xor_sync(0xffffffffu, a2, 16);
        float b3 = __shfl_xor_sync(0xffffffffu, a3, 16);
        float Mn = fmaxf(m, mo);
        float fs = __expf(m - Mn);
        float fo = __expf(mo - Mn);
        l  = l * fs + lo * fo;
        a0 = a0 * fs + b0 * fo;
        a1 = a1 * fs + b1 * fo;
        a2 = a2 * fs + b2 * fo;
        a3 = a3 * fs + b3 * fo;
        m  = Mn;
    }
    if (lane == 0) { s_m[w] = m; s_l[w] = l; }
    if (lane < 16) {
        s_acc[w * DD + 4 * li + 0] = a0;
        s_acc[w * DD + 4 * li + 1] = a1;
        s_acc[w * DD + 4 * li + 2] = a2;
        s_acc[w * DD + 4 * li + 3] = a3;
    }
    __syncthreads();

    float* part = g_part + (size_t)bx * PART_STRIDE;

    // warp 0: merge 16 per-warp (m,l)
    if (w == 0) {
        float mw = (lane < W1) ? s_m[lane] : -3.0e38f;
        float M  = mw;
        #pragma unroll
        for (int o = 16; o; o >>= 1) M = fmaxf(M, __shfl_xor_sync(0xffffffffu, M, o));
        float f  = __expf(mw - M);
        float lw = (lane < W1) ? s_l[lane] * f : 0.0f;
        #pragma unroll
        for (int o = 16; o; o >>= 1) lw += __shfl_xor_sync(0xffffffffu, lw, o);
        if (lane < W1) s_f[lane] = f;
        if (lane == 0) { part[0] = M; part[1] = lw; }
    }
    __syncthreads();

    if (tid < DD) {
        float acc = 0.0f;
        #pragma unroll
        for (int ww = 0; ww < W1; ww++)
            acc = fmaf(s_acc[ww * DD + tid], s_f[ww], acc);
        part[2 + tid] = acc;
    }
}

__global__ __launch_bounds__(256)
void ra_pass2(float* __restrict__ out,
              float* __restrict__ alpha)   // holds raw scores on entry
{
    const int bx    = blockIdx.x;
    const int b     = bx >> 2;
    const int chunk = bx & 3;
    const int tid   = threadIdx.x;

    const float* P = g_part + (size_t)(b * CC) * PART_STRIDE;

    float mc[CC], lc[CC];
    #pragma unroll
    for (int c = 0; c < CC; c++) {
        mc[c] = P[c * PART_STRIDE + 0];
        lc[c] = P[c * PART_STRIDE + 1];
    }
    float M = mc[0];
    #pragma unroll
    for (int c = 1; c < CC; c++) M = fmaxf(M, mc[c]);
    float L = 0.0f, fc[CC];
    #pragma unroll
    for (int c = 0; c < CC; c++) { fc[c] = __expf(mc[c] - M); L += lc[c] * fc[c]; }
    const float invL = 1.0f / L;

    if (chunk == 0 && tid < DD) {
        float acc = 0.0f;
        #pragma unroll
        for (int c = 0; c < CC; c++)
            acc = fmaf(P[c * PART_STRIDE + 2 + tid], fc[c], acc);
        out[b * DD + tid] = acc * invL;
    }

    // scores -> alpha, in place
    float4* ap = reinterpret_cast<float4*>(alpha + (size_t)b * SS + (size_t)chunk * ROWS_CTA);
    #pragma unroll
    for (int i = tid; i < ROWS_CTA / 4; i += 256) {
        float4 s = ap[i];
        s.x = __expf(s.x - M) * invL;
        s.y = __expf(s.y - M) * invL;
        s.z = __expf(s.z - M) * invL;
        s.w = __expf(s.w - M) * invL;
        ap[i] = s;
    }
}

extern "C" void kernel_launch(void* const* d_in, const int* in_sizes, int n_in,
                              void* d_out, int out_size)
{
    const float* x = (const float*)d_in[0];   // (B, S, D) fp32
    const float* v = (const float*)d_in[1];   // (D, 1)    fp32
    float* out   = (float*)d_out;
    float* alpha = out + (size_t)BB * DD;

    ra_pass1<<<BB * CC, T1>>>(x, v, alpha);
    ra_pass2<<<BB * CC, 256>>>(out, alpha);
}

// round 14
// speedup vs baseline: 1.0030x; 1.0030x over previous
#include <cuda_runtime.h>
#include <math.h>

// RecurrentAttention: B=128, S=8192, D=64
//   scores[b,s] = sum_d x[b,s,d] * v[d]
//   alpha[b,s]  = softmax_s(scores)
//   out[b,d]    = sum_s alpha[b,s] * x[b,s,d]
// Output layout: d_out[0..B*D) = out, d_out[B*D..B*D+B*S) = alpha.
//
// Two-kernel split-S design:
//  K1: grid = B*C CTAs (C=4 chunks of S), 512 threads. Single pass over x.
//      Half-warp-per-row scheme: one float4 LDG covers 2 rows (lanes 0-15 row
//      2j, lanes 16-31 row 2j+1, 4 dims/lane). Dot reduce = 4 shuffles for 2
//      rows. Branchless online softmax. Raw scores written (coalesced) into
//      the alpha buffer; per-CTA partial (m, l, acc[64]) to __device__ scratch.
//  K2: merge the C partials per batch, write out[b,:], transform raw scores
//      in-place into alpha = exp(s - M) / L.

#define BB 128
#define SS 8192
#define DD 64
#define CC 4                        // chunks per batch
#define ROWS_CTA (SS / CC)          // 2048
#define T1 512
#define W1 (T1 / 32)                // 16 warps
#define RPW (ROWS_CTA / W1)         // 128 rows per warp
#define PART_STRIDE 68              // m, l, acc[64], pad

__device__ float g_part[BB * CC * PART_STRIDE];

__global__ __launch_bounds__(T1, 3)
void ra_pass1(const float* __restrict__ x,
              const float* __restrict__ v,
              float* __restrict__ alpha)   // raw scores written here
{
    __shared__ float s_m[W1];
    __shared__ float s_l[W1];
    __shared__ float s_f[W1];
    __shared__ float s_acc[W1 * DD];

    const int bx    = blockIdx.x;
    const int b     = bx >> 2;
    const int chunk = bx & 3;
    const int tid   = threadIdx.x;
    const int w     = tid >> 5;
    const int lane  = tid & 31;
    const int li    = lane & 15;    // lane within half-warp
    const int h     = lane >> 4;    // which half (row parity)

    // 4 dims per lane
    const float4 vv = reinterpret_cast<const float4*>(v)[li];

    // this warp's 128 rows
    const float4* xp =
        reinterpret_cast<const float4*>(
            x + ((size_t)b * SS + (size_t)chunk * ROWS_CTA + (size_t)w * RPW) * DD)
        + (size_t)h * (DD / 4) + li;
    // row r (even base) lives at offset r*(DD/4)=r*16 float4

    float* score_out = alpha + (size_t)b * SS + (size_t)chunk * ROWS_CTA + (size_t)w * RPW;

    float m = -3.0e38f, l = 0.0f;
    float a0 = 0.f, a1 = 0.f, a2 = 0.f, a3 = 0.f;

    #pragma unroll
    for (int blk = 0; blk < RPW; blk += 32) {       // 32-row blocks
        float sreg = 0.0f;
        #pragma unroll
        for (int jj = 0; jj < 16; jj += 4) {        // row-pairs, 4 at a time
            float4 xv[4];
            #pragma unroll
            for (int u = 0; u < 4; u++)
                xv[u] = xp[(blk + 2 * (jj + u)) * (DD / 4)];

            #pragma unroll
            for (int u = 0; u < 4; u++) {
                float p = fmaf(xv[u].x, vv.x,
                          fmaf(xv[u].y, vv.y,
                          fmaf(xv[u].z, vv.z, xv[u].w * vv.w)));
                p += __shfl_xor_sync(0xffffffffu, p, 1);
                p += __shfl_xor_sync(0xffffffffu, p, 2);
                p += __shfl_xor_sync(0xffffffffu, p, 4);
                p += __shfl_xor_sync(0xffffffffu, p, 8);
                // all 16 lanes of each half now hold their row's score

                if (li == jj + u) sreg = p;         // rotate into writer lane

                // branchless online update (identical instrs, per-half data)
                float Mn   = fmaxf(m, p);
                float corr = __expf(m - Mn);
                float wt   = __expf(p - Mn);
                l  = fmaf(l,  corr, wt);
                a0 = fmaf(a0, corr, wt * xv[u].x);
                a1 = fmaf(a1, corr, wt * xv[u].y);
                a2 = fmaf(a2, corr, wt * xv[u].z);
                a3 = fmaf(a3, corr, wt * xv[u].w);
                m  = Mn;
            }
        }
        // coalesced 32-lane score write: lane L -> row blk + 2*(L&15) + (L>>4)
        score_out[blk + 2 * li + h] = sreg;
    }

    // merge the two half-warps (same dims, different rows)
    {
        float mo = __shfl_xor_sync(0xffffffffu, m,  16);
        float lo = __shfl_xor_sync(0xffffffffu, l,  16);
        float b0 = __shfl_xor_sync(0xffffffffu, a0, 16);
        float b1 = __shfl_xor_sync(0xffffffffu, a1, 16);
        float b2 = __shfl_xor_sync(0xffffffffu, a2, 16);
        float b3 = __shfl_xor_sync(0xffffffffu, a3, 16);
        float Mn = fmaxf(m, mo);
        float fs = __expf(m - Mn);
        float fo = __expf(mo - Mn);
        l  = l * fs + lo * fo;
        a0 = a0 * fs + b0 * fo;
        a1 = a1 * fs + b1 * fo;
        a2 = a2 * fs + b2 * fo;
        a3 = a3 * fs + b3 * fo;
        m  = Mn;
    }
    if (lane == 0) { s_m[w] = m; s_l[w] = l; }
    if (lane < 16) {
        s_acc[w * DD + 4 * li + 0] = a0;
        s_acc[w * DD + 4 * li + 1] = a1;
        s_acc[w * DD + 4 * li + 2] = a2;
        s_acc[w * DD + 4 * li + 3] = a3;
    }
    __syncthreads();

    float* part = g_part + (size_t)bx * PART_STRIDE;

    // warp 0: merge 16 per-warp (m,l)
    if (w == 0) {
        float mw = (lane < W1) ? s_m[lane] : -3.0e38f;
        float M  = mw;
        #pragma unroll
        for (int o = 16; o; o >>= 1) M = fmaxf(M, __shfl_xor_sync(0xffffffffu, M, o));
        float f  = __expf(mw - M);
        float lw = (lane < W1) ? s_l[lane] * f : 0.0f;
        #pragma unroll
        for (int o = 16; o; o >>= 1) lw += __shfl_xor_sync(0xffffffffu, lw, o);
        if (lane < W1) s_f[lane] = f;
        if (lane == 0) { part[0] = M; part[1] = lw; }
    }
    __syncthreads();

    if (tid < DD) {
        float acc = 0.0f;
        #pragma unroll
        for (int ww = 0; ww < W1; ww++)
            acc = fmaf(s_acc[ww * DD + tid], s_f[ww], acc);
        part[2 + tid] = acc;
    }
}

__global__ __launch_bounds__(256)
void ra_pass2(float* __restrict__ out,
              float* __restrict__ alpha)   // holds raw scores on entry
{
    const int bx    = blockIdx.x;
    const int b     = bx >> 2;
    const int chunk = bx & 3;
    const int tid   = threadIdx.x;

    const float* P = g_part + (size_t)(b * CC) * PART_STRIDE;

    float mc[CC], lc[CC];
    #pragma unroll
    for (int c = 0; c < CC; c++) {
        mc[c] = P[c * PART_STRIDE + 0];
        lc[c] = P[c * PART_STRIDE + 1];
    }
    float M = mc[0];
    #pragma unroll
    for (int c = 1; c < CC; c++) M = fmaxf(M, mc[c]);
    float L = 0.0f, fc[CC];
    #pragma unroll
    for (int c = 0; c < CC; c++) { fc[c] = __expf(mc[c] - M); L += lc[c] * fc[c]; }
    const float invL = 1.0f / L;

    if (chunk == 0 && tid < DD) {
        float acc = 0.0f;
        #pragma unroll
        for (int c = 0; c < CC; c++)
            acc = fmaf(P[c * PART_STRIDE + 2 + tid], fc[c], acc);
        out[b * DD + tid] = acc * invL;
    }

    // scores -> alpha, in place
    float4* ap = reinterpret_cast<float4*>(alpha + (size_t)b * SS + (size_t)chunk * ROWS_CTA);
    #pragma unroll
    for (int i = tid; i < ROWS_CTA / 4; i += 256) {
        float4 s = ap[i];
        s.x = __expf(s.x - M) * invL;
        s.y = __expf(s.y - M) * invL;
        s.z = __expf(s.z - M) * invL;
        s.w = __expf(s.w - M) * invL;
        ap[i] = s;
    }
}

extern "C" void kernel_launch(void* const* d_in, const int* in_sizes, int n_in,
                              void* d_out, int out_size)
{
    const float* x = (const float*)d_in[0];   // (B, S, D) fp32
    const float* v = (const float*)d_in[1];   // (D, 1)    fp32
    float* out   = (float*)d_out;
    float* alpha = out + (size_t)BB * DD;

    ra_pass1<<<BB * CC, T1>>>(x, v, alpha);
    ra_pass2<<<BB * CC, 256>>>(out, alpha);
}

// round 15
// speedup vs baseline: 1.4208x; 1.4165x over previous
#include <cuda_runtime.h>
#include <math.h>

// RecurrentAttention: B=128, S=8192, D=64
//   scores[b,s] = sum_d x[b,s,d] * v[d]
//   alpha[b,s]  = softmax_s(scores)
//   out[b,d]    = sum_s alpha[b,s] * x[b,s,d]
// Output layout: d_out[0..B*D) = out, d_out[B*D..) = alpha.
//
// Fine-grained split-S (C=16):
//  pass1: 2048 CTAs x 256 thr. Per-warp inner loop identical to the proven
//         R8 kernel (float2 per lane, 8 loads in flight, 5-shuffle dot
//         reduce, warp-uniform branchy online-softmax update). Raw scores
//         staged in SMEM, dumped coalesced into the alpha buffer. Per-CTA
//         partial (m, l, acc[64]) -> __device__ scratch.
//  pass2: per batch merge 16 partials, write out[b,:], transform raw
//         scores in place into alpha.

#define BB 128
#define SS 8192
#define DD 64
#define CC 16
#define ROWS_CTA (SS / CC)          // 512
#define T1 256
#define W1 (T1 / 32)                // 8 warps
#define RPW (ROWS_CTA / W1)         // 64 rows per warp
#define UU 8
#define PART_STRIDE 66              // m, l, acc[64]

__device__ float g_part[BB * CC * PART_STRIDE];

__global__ __launch_bounds__(T1, 6)
void ra_pass1(const float* __restrict__ x,
              const float* __restrict__ v,
              float* __restrict__ alpha)   // raw scores written here
{
    __shared__ float s_scores[ROWS_CTA];   // 2 KB
    __shared__ float s_m[W1];
    __shared__ float s_l[W1];
    __shared__ float s_f[W1];
    __shared__ float s_acc[W1 * DD];       // 2 KB

    const int bx    = blockIdx.x;
    const int b     = bx >> 4;             // / CC
    const int chunk = bx & 15;
    const int tid   = threadIdx.x;
    const int w     = tid >> 5;
    const int lane  = tid & 31;

    const float v0 = v[2 * lane];
    const float v1 = v[2 * lane + 1];

    // warp w owns rows [chunk*512 + w*64, +64)
    const float2* xrow =
        reinterpret_cast<const float2*>(
            x + ((size_t)b * SS + (size_t)chunk * ROWS_CTA + (size_t)w * RPW) * DD) + lane;

    float m  = -3.0e38f;
    float l  = 0.0f;
    float a0 = 0.0f, a1 = 0.0f;

    const int score_base = w * RPW;

    for (int i = 0; i < RPW; i += UU) {
        float2 xv[UU];
        #pragma unroll
        for (int u = 0; u < UU; u++)
            xv[u] = xrow[(i + u) * (DD / 2)];

        #pragma unroll
        for (int u = 0; u < UU; u++) {
            float p = fmaf(xv[u].x, v0, xv[u].y * v1);
            p += __shfl_xor_sync(0xffffffffu, p, 16);
            p += __shfl_xor_sync(0xffffffffu, p, 8);
            p += __shfl_xor_sync(0xffffffffu, p, 4);
            p += __shfl_xor_sync(0xffffffffu, p, 2);
            p += __shfl_xor_sync(0xffffffffu, p, 1);

            if (lane == 0) s_scores[score_base + i + u] = p;

            // warp-uniform branch (p, m identical on all lanes)
            if (p <= m) {
                float wt = __expf(p - m);
                l += wt;
                a0 = fmaf(wt, xv[u].x, a0);
                a1 = fmaf(wt, xv[u].y, a1);
            } else {
                float corr = __expf(m - p);
                l  = fmaf(l,  corr, 1.0f);
                a0 = fmaf(a0, corr, xv[u].x);
                a1 = fmaf(a1, corr, xv[u].y);
                m  = p;
            }
        }
    }

    if (lane == 0) { s_m[w] = m; s_l[w] = l; }
    s_acc[w * DD + 2 * lane]     = a0;
    s_acc[w * DD + 2 * lane + 1] = a1;
    __syncthreads();

    float* part = g_part + (size_t)bx * PART_STRIDE;

    // warp 0: merge the 8 per-warp (m,l) states
    if (w == 0) {
        float mw = (lane < W1) ? s_m[lane] : -3.0e38f;
        float M  = mw;
        #pragma unroll
        for (int o = 16; o; o >>= 1) M = fmaxf(M, __shfl_xor_sync(0xffffffffu, M, o));
        float f  = __expf(mw - M);
        float lw = (lane < W1) ? s_l[lane] * f : 0.0f;
        #pragma unroll
        for (int o = 16; o; o >>= 1) lw += __shfl_xor_sync(0xffffffffu, lw, o);
        if (lane < W1) s_f[lane] = f;
        if (lane == 0) { part[0] = M; part[1] = lw; }
    }
    __syncthreads();

    if (tid < DD) {
        float acc = 0.0f;
        #pragma unroll
        for (int ww = 0; ww < W1; ww++)
            acc = fmaf(s_acc[ww * DD + tid], s_f[ww], acc);
        part[2 + tid] = acc;
    }

    // coalesced raw-score dump: 128 threads x float4 = 512 floats
    if (tid < ROWS_CTA / 4) {
        float4 sc = reinterpret_cast<const float4*>(s_scores)[tid];
        reinterpret_cast<float4*>(
            alpha + (size_t)b * SS + (size_t)chunk * ROWS_CTA)[tid] = sc;
    }
}

#define T2 256
#define CPB 8                        // pass2 CTAs per batch
#define SPC (SS / CPB)               // 1024 scores per CTA

__global__ __launch_bounds__(T2)
void ra_pass2(float* __restrict__ out,
              float* __restrict__ alpha)   // raw scores on entry
{
    const int bx  = blockIdx.x;
    const int b   = bx >> 3;
    const int c8  = bx & 7;
    const int tid = threadIdx.x;

    const float* P = g_part + (size_t)(b * CC) * PART_STRIDE;

    float mc[CC], lc[CC];
    #pragma unroll
    for (int c = 0; c < CC; c++) {
        mc[c] = P[c * PART_STRIDE + 0];
        lc[c] = P[c * PART_STRIDE + 1];
    }
    float M = mc[0];
    #pragma unroll
    for (int c = 1; c < CC; c++) M = fmaxf(M, mc[c]);
    float L = 0.0f, fc[CC];
    #pragma unroll
    for (int c = 0; c < CC; c++) { fc[c] = __expf(mc[c] - M); L += lc[c] * fc[c]; }
    const float invL = 1.0f / L;

    if (c8 == 0 && tid < DD) {
        float acc = 0.0f;
        #pragma unroll
        for (int c = 0; c < CC; c++)
            acc = fmaf(P[c * PART_STRIDE + 2 + tid], fc[c], acc);
        out[b * DD + tid] = acc * invL;
    }

    // scores -> alpha in place: one float4 per thread
    float4* ap = reinterpret_cast<float4*>(alpha + (size_t)b * SS + (size_t)c8 * SPC);
    float4 s = ap[tid];
    s.x = __expf(s.x - M) * invL;
    s.y = __expf(s.y - M) * invL;
    s.z = __expf(s.z - M) * invL;
    s.w = __expf(s.w - M) * invL;
    ap[tid] = s;
}

extern "C" void kernel_launch(void* const* d_in, const int* in_sizes, int n_in,
                              void* d_out, int out_size)
{
    const float* x = (const float*)d_in[0];   // (B, S, D) fp32
    const float* v = (const float*)d_in[1];   // (D, 1)    fp32
    float* out   = (float*)d_out;
    float* alpha = out + (size_t)BB * DD;

    ra_pass1<<<BB * CC, T1>>>(x, v, alpha);
    ra_pass2<<<BB * CPB, T2>>>(out, alpha);
}